// round 4
// baseline (speedup 1.0000x reference)
#include <cuda_runtime.h>

// EMA alpha=0.2; out[i] = e_{idx}, idx = max(len[i],1)-1.
// Truncated 48-tap trailing window: tail weight <= 0.8^44 ~ 5.4e-5 relative,
// 20x under the 1e-3 threshold. Rows with idx < 48 are computed exactly.
//
// Layout: 16-lane row groups, 2 rows/warp -> 8192 warps = single wave.
// Lanes 0..11 of each group each do ONE aligned LDG.128 (float4) covering the
// 48-float window; lanes 12..15 idle (contribute 0). Window start aligned up
// to 4 (keeps s >= n-47, so all taps with weight > 0.8^47 included) and
// clamped to [0, T-48] so the load stays in-row.

#define LOG2_08 (-0.32192809488736234787f) // log2(0.8)

__global__ void __launch_bounds__(256)
ema_last_kernel(const float* __restrict__ x,
                const int* __restrict__ valid_len,
                float* __restrict__ out,
                int B, int T)
{
    int warp = (int)((blockIdx.x * blockDim.x + threadIdx.x) >> 5);
    int lane = threadIdx.x & 31;
    int sub  = lane & 15;               // lane within 16-lane row group
    int row  = warp * 2 + (lane >> 4);
    if (row >= B) return;

    int len = valid_len[row];
    int n   = (len > 1 ? len : 1) - 1;  // target index idx = L-1

    // Aligned window start: s in [n-47, n-44] (or 0), 4-aligned, in-row.
    int s = n - 47;
    s = (s > 0) ? ((s + 3) & ~3) : 0;
    if (s > T - 48) s = T - 48;

    float acc = 0.0f;
    if (sub < 12) {
        const float4 v =
            reinterpret_cast<const float4*>(x + (size_t)row * (size_t)T + s)[sub];

        int j0 = s + 4 * sub;                    // global index of v.x
        // tap weight: 0.2 * 0.8^(n - j)   (seed j==0 gets x5 -> 0.8^n)
        float wb = 0.2f * exp2f((float)(n - j0) * LOG2_08);
        float w0 = wb;
        float w1 = wb * 1.25f;
        float w2 = wb * 1.5625f;
        float w3 = wb * 1.953125f;

        if (j0 + 0 == 0) w0 *= 5.0f;   if (j0 + 0 > n) w0 = 0.0f;
        if (j0 + 1 == 0) w1 *= 5.0f;   if (j0 + 1 > n) w1 = 0.0f;
        if (j0 + 2 == 0) w2 *= 5.0f;   if (j0 + 2 > n) w2 = 0.0f;
        if (j0 + 3 == 0) w3 *= 5.0f;   if (j0 + 3 > n) w3 = 0.0f;

        acc = fmaf(w0, v.x, fmaf(w1, v.y, fmaf(w2, v.z, w3 * v.w)));
    }

    // reduce over the 16-lane group (xor offsets stay within the group)
#pragma unroll
    for (int off = 8; off > 0; off >>= 1)
        acc += __shfl_xor_sync(0xffffffffu, acc, off);

    if (sub == 0) out[row] = acc;
}

extern "C" void kernel_launch(void* const* d_in, const int* in_sizes, int n_in,
                              void* d_out, int out_size)
{
    const float* pop_history = (const float*)d_in[0];
    const int*   valid_len   = (const int*)d_in[1];
    float*       out         = (float*)d_out;

    int B = in_sizes[1];               // 16384
    int T = in_sizes[0] / in_sizes[1]; // 2048

    int threads = 256;                 // 8 warps = 16 rows per block
    int rows_per_block = (threads / 32) * 2;
    int blocks = (B + rows_per_block - 1) / rows_per_block;   // 1024
    ema_last_kernel<<<blocks, threads>>>(pop_history, valid_len, out, B, T);
}

// round 5
// speedup vs baseline: 1.0435x; 1.0435x over previous
#include <cuda_runtime.h>

// EMA alpha=0.2; out[i] = e_{idx}, idx = max(len[i],1)-1.
// 64-tap trailing window (tail weight 0.8^63 ~ 8e-7 << 1e-3 threshold);
// rows with idx < 64 computed exactly from x_0.
//
// Structure (R5): 8-lane row groups, 4 rows per warp -> 4096 warps, 512 CTAs.
// Each lane issues TWO independent aligned LDG.128 (float4) covering the
// 64-float window (8 lanes x 8 floats). Halves the warp count vs R4 (less
// ramp/schedule work) while keeping the 2-dependent-DRAM-trip chain and
// doubling per-lane MLP. Window start aligned up to 4 (keeps s >= n-63) and
// clamped to [0, T-64] so both loads stay in-row.

#define LOG2_08 (-0.32192809488736234787f)  // log2(0.8)
#define INV08_32 1262.1774483536189f        // 0.8^-32 = 1.25^32

__global__ void __launch_bounds__(256)
ema_last_kernel(const float* __restrict__ x,
                const int* __restrict__ valid_len,
                float* __restrict__ out,
                int B, int T)
{
    int warp = (int)((blockIdx.x * blockDim.x + threadIdx.x) >> 5);
    int lane = threadIdx.x & 31;
    int sub  = lane & 7;                 // lane within 8-lane row group
    int row  = warp * 4 + (lane >> 3);
    if (row >= B) return;

    int len = valid_len[row];
    int n   = (len > 1 ? len : 1) - 1;   // target index idx = L-1

    // Aligned window start: s in [n-63, n-60] (or 0), 4-aligned, in-row.
    int s = n - 63;
    s = (s > 0) ? ((s + 3) & ~3) : 0;
    if (s > T - 64) s = T - 64;

    const float4* p = reinterpret_cast<const float4*>(x + (size_t)row * (size_t)T + s);
    // Two independent loads issue back-to-back (MLP=2).
    float4 a = p[sub];
    float4 b = p[sub + 8];

    int ja = s + 4 * sub;                // global index of a.x
    int jb = ja + 32;                    // global index of b.x

    // tap weight: 0.2 * 0.8^(n - j); seed (j==0) coefficient is 0.8^n = 5x that.
    float wa = 0.2f * exp2f((float)(n - ja) * LOG2_08);
    float wb = wa * INV08_32;            // 0.2 * 0.8^(n - jb)

    float a0 = wa,            a1 = wa * 1.25f,
          a2 = wa * 1.5625f,  a3 = wa * 1.953125f;
    float b0 = wb,            b1 = wb * 1.25f,
          b2 = wb * 1.5625f,  b3 = wb * 1.953125f;

    if (ja + 0 == 0) a0 *= 5.0f;   if (ja + 0 > n) a0 = 0.0f;
    if (ja + 1 == 0) a1 *= 5.0f;   if (ja + 1 > n) a1 = 0.0f;
    if (ja + 2 == 0) a2 *= 5.0f;   if (ja + 2 > n) a2 = 0.0f;
    if (ja + 3 == 0) a3 *= 5.0f;   if (ja + 3 > n) a3 = 0.0f;
    // b taps can't be the seed unless jb==0 (impossible: jb >= 32)
    if (jb + 0 > n) b0 = 0.0f;
    if (jb + 1 > n) b1 = 0.0f;
    if (jb + 2 > n) b2 = 0.0f;
    if (jb + 3 > n) b3 = 0.0f;

    float acc = fmaf(a0, a.x, fmaf(a1, a.y, fmaf(a2, a.z, a3 * a.w)));
    acc = fmaf(b0, b.x, fmaf(b1, b.y, fmaf(b2, b.z, fmaf(b3, b.w, acc))));

    // reduce over the 8-lane group (xor offsets stay within the group)
#pragma unroll
    for (int off = 4; off > 0; off >>= 1)
        acc += __shfl_xor_sync(0xffffffffu, acc, off);

    if (sub == 0) out[row] = acc;
}

extern "C" void kernel_launch(void* const* d_in, const int* in_sizes, int n_in,
                              void* d_out, int out_size)
{
    const float* pop_history = (const float*)d_in[0];
    const int*   valid_len   = (const int*)d_in[1];
    float*       out         = (float*)d_out;

    int B = in_sizes[1];               // 16384
    int T = in_sizes[0] / in_sizes[1]; // 2048

    int threads = 256;                 // 8 warps = 32 rows per block
    int rows_per_block = (threads / 32) * 4;
    int blocks = (B + rows_per_block - 1) / rows_per_block;   // 512
    ema_last_kernel<<<blocks, threads>>>(pop_history, valid_len, out, B, T);
}